// round 6
// baseline (speedup 1.0000x reference)
#include <cuda_runtime.h>
#include <cuda_bf16.h>

// Problem constants (fixed by the reference)
#define NROWS 8192
#define NCOLS 8192
#define RB 32
#define CB 32
#define HID 100
#define DIO (RB*CB)
#define SPLITS 16                      // row-slots per (rb,cb) block
#define NITEMS (RB*CB*SPLITS)          // 16384 per-warp work items
#define NB_CTAS 296                    // 2 CTAs/SM x 148 SMs, co-residency guaranteed

// Scratch (no cudaMalloc allowed)
__device__ float g_blk[RB*CB];
__device__ int   g_rowb[RB+1];
__device__ int   g_colb[CB+1];
__device__ int   g_work;
__device__ unsigned g_bar_arrive = 0;
__device__ volatile unsigned g_bar_gen = 0;

// Generation-based grid barrier: safe across graph replays (state self-resets),
// deadlock-free because all NB_CTAS are co-resident (launch_bounds(256,2)).
__device__ __forceinline__ void grid_barrier() {
    __syncthreads();
    if (threadIdx.x == 0) {
        __threadfence();
        unsigned gen = g_bar_gen;
        unsigned a = atomicAdd(&g_bar_arrive, 1u);
        if (a == NB_CTAS - 1u) {
            atomicExch(&g_bar_arrive, 0u);
            __threadfence();
            g_bar_gen = gen + 1u;
        } else {
            while (g_bar_gen == gen) { }
            __threadfence();
        }
    }
    __syncthreads();
}

__global__ __launch_bounds__(256, 2)
void k_fused(const float* __restrict__ X,
             const int* __restrict__ row_ids,
             const int* __restrict__ col_ids,
             const float* __restrict__ W1, const float* __restrict__ b1,
             const float* __restrict__ W2, const float* __restrict__ b2,
             const float* __restrict__ W3, const float* __restrict__ b3,
             float* __restrict__ out) {
    __shared__ int   srow[RB + 1];
    __shared__ int   scol[CB + 1];
    // MLP scratch (CTA 0 only, phase C)
    __shared__ float xs[DIO];
    __shared__ float h1p[800];
    __shared__ float h2p[1000];
    __shared__ float h1[HID];
    __shared__ float h2[HID];

    const int t = threadIdx.x;
    const int warp = t >> 5, lane = t & 31;

    // ---------------- Phase A: setup (distributed) ----------------
    if (blockIdx.x < 32) {
        const bool rowpass = (blockIdx.x < 16);
        const int  slice   = rowpass ? blockIdx.x : (blockIdx.x - 16);
        const int  nb  = rowpass ? RB : CB;
        const int  n   = rowpass ? NROWS : NCOLS;
        const int* ids = rowpass ? row_ids : col_ids;
        int*   bnd = rowpass ? g_rowb : g_colb;
        float* o   = out + DIO + (rowpass ? 0 : (RB + 1));
        const int i = slice * 512 + t * 2;
        #pragma unroll
        for (int d = 0; d < 2; d++) {
            int g = i + d;
            if (g < n) {
                int cur  = ids[g];
                int prev = (g == 0) ? -1 : ids[g - 1];
                for (int k = prev + 1; k <= cur; k++) { bnd[k] = g; o[k] = (float)g; }
                if (g == n - 1)
                    for (int k = cur + 1; k <= nb; k++) { bnd[k] = n; o[k] = (float)n; }
            }
        }
    } else if (blockIdx.x == 32) {
        for (int j = t; j < DIO; j += 256) g_blk[j] = 0.0f;
    } else if (blockIdx.x == 33 && t == 0) {
        g_work = 0;
    }

    grid_barrier();

    // boundary arrays -> smem (L2-hot after barrier)
    if (t <= RB) srow[t] = g_rowb[t];
    else if (t >= 64 && t <= 64 + CB) scol[t - 64] = g_colb[t - 64];
    __syncthreads();

    // ---------------- Phase B: per-warp dynamic block-sum ----------------
    for (;;) {
        int item;
        if (lane == 0) item = atomicAdd(&g_work, 1);
        item = __shfl_sync(0xFFFFFFFFu, item, 0);
        if (item >= NITEMS) break;

        const int rb = item >> 9;
        const int cb = (item >> 4) & 31;
        const int ws = item & (SPLITS - 1);
        const int rlo = srow[rb], rhi = srow[rb + 1];
        const int clo = scol[cb], chi = scol[cb + 1];

        // 16B-aligned body [ca, ce), scalar head and tail
        int ca = (clo + 3) & ~3; if (ca > chi) ca = chi;
        int ce = chi & ~3;       if (ce < ca)  ce = ca;
        const int hN = ca - clo, tN = chi - ce;
        const int c4lo = ca >> 2, c4hi = ce >> 2;

        float a0 = 0.f, a1 = 0.f, a2 = 0.f, a3 = 0.f;
        int r = rlo + ws;

        // 4-row unrolled groups (rows strided by SPLITS, independent loads)
        for (; r + 3 * SPLITS < rhi; r += 4 * SPLITS) {
            const float* q0 = X + (size_t)r * NCOLS;
            const float* q1 = X + (size_t)(r +     SPLITS) * NCOLS;
            const float* q2 = X + (size_t)(r + 2 * SPLITS) * NCOLS;
            const float* q3 = X + (size_t)(r + 3 * SPLITS) * NCOLS;
            if (lane < hN) {
                a0 += q0[clo + lane]; a1 += q1[clo + lane];
                a2 += q2[clo + lane]; a3 += q3[clo + lane];
            }
            const float4* p0 = (const float4*)q0;
            const float4* p1 = (const float4*)q1;
            const float4* p2 = (const float4*)q2;
            const float4* p3 = (const float4*)q3;
            for (int c = c4lo + lane; c < c4hi; c += 32) {
                float4 v0 = p0[c];
                float4 v1 = p1[c];
                float4 v2 = p2[c];
                float4 v3 = p3[c];
                a0 += (v0.x + v0.y) + (v0.z + v0.w);
                a1 += (v1.x + v1.y) + (v1.z + v1.w);
                a2 += (v2.x + v2.y) + (v2.z + v2.w);
                a3 += (v3.x + v3.y) + (v3.z + v3.w);
            }
            if (lane < tN) {
                a0 += q0[ce + lane]; a1 += q1[ce + lane];
                a2 += q2[ce + lane]; a3 += q3[ce + lane];
            }
        }
        for (; r < rhi; r += SPLITS) {
            const float* q0 = X + (size_t)r * NCOLS;
            if (lane < hN) a0 += q0[clo + lane];
            const float4* p0 = (const float4*)q0;
            for (int c = c4lo + lane; c < c4hi; c += 32) {
                float4 v0 = p0[c];
                a0 += (v0.x + v0.y) + (v0.z + v0.w);
            }
            if (lane < tN) a0 += q0[ce + lane];
        }

        float acc = (a0 + a1) + (a2 + a3);
        #pragma unroll
        for (int o = 16; o; o >>= 1) acc += __shfl_xor_sync(0xFFFFFFFFu, acc, o);
        if (lane == 0) atomicAdd(&g_blk[rb * CB + cb], acc);   // REDG, no return dep
    }

    grid_barrier();

    // ---------------- Phase C: MLP (CTA 0 only) ----------------
    if (blockIdx.x != 0) return;

    // block mean (256 threads -> 4 bins each)
    #pragma unroll
    for (int d = 0; d < 4; d++) {
        int b = t + d * 256;
        int rb = b >> 5, cbi = b & 31;
        float rc = (float)(srow[rb + 1] - srow[rb]);
        float cc = (float)(scol[cbi + 1] - scol[cbi]);
        float cnt = fmaxf(rc * cc, 1.0f);
        xs[b] = g_blk[b] / cnt;
    }
    __syncthreads();

    // layer 1: h1 = relu(x @ W1 + b1), x[1024], W1[1024,100]; 8 K-slices x 100
    for (int u = t; u < 800; u += 256) {
        const int j  = u % HID;
        const int i0 = (u / HID) * 128;
        float acc = 0.f;
        #pragma unroll 16
        for (int i = 0; i < 128; i++)
            acc += xs[i0 + i] * W1[(size_t)(i0 + i) * HID + j];
        h1p[u] = acc;
    }
    __syncthreads();
    if (t < HID) {
        float a = b1[t];
        #pragma unroll
        for (int sl = 0; sl < 8; sl++) a += h1p[sl * HID + t];
        h1[t] = fmaxf(a, 0.f);
    }
    __syncthreads();

    // layer 2: h2 = relu(h1 @ W2 + b2), W2[100,100]; 10 K-slices x 100
    for (int u = t; u < 1000; u += 256) {
        const int j  = u % HID;
        const int i0 = (u / HID) * 10;
        float acc = 0.f;
        #pragma unroll
        for (int i = 0; i < 10; i++)
            acc += h1[i0 + i] * W2[(i0 + i) * HID + j];
        h2p[u] = acc;
    }
    __syncthreads();
    if (t < HID) {
        float a = b2[t];
        #pragma unroll
        for (int sl = 0; sl < 10; sl++) a += h2p[sl * HID + t];
        h2[t] = fmaxf(a, 0.f);
    }
    __syncthreads();

    // layer 3: out = sigmoid(h2 @ W3 + b3), W3[100,1024]
    #pragma unroll
    for (int d = 0; d < 4; d++) {
        int j = t + d * 256;
        float a = b3[j];
        #pragma unroll 20
        for (int i = 0; i < HID; i++) a += h2[i] * W3[(size_t)i * DIO + j];
        out[j] = 1.0f / (1.0f + __expf(-a));
    }
}

extern "C" void kernel_launch(void* const* d_in, const int* in_sizes, int n_in,
                              void* d_out, int out_size) {
    const float* X       = (const float*)d_in[0];
    const int*   row_ids = (const int*)  d_in[1];
    const int*   col_ids = (const int*)  d_in[2];
    const float* W1      = (const float*)d_in[3];
    const float* b1      = (const float*)d_in[4];
    const float* W2      = (const float*)d_in[5];
    const float* b2      = (const float*)d_in[6];
    const float* W3      = (const float*)d_in[7];
    const float* b3      = (const float*)d_in[8];
    float* out = (float*)d_out;

    k_fused<<<NB_CTAS, 256>>>(X, row_ids, col_ids, W1, b1, W2, b2, W3, b3, out);
}

// round 7
// speedup vs baseline: 1.1512x; 1.1512x over previous
#include <cuda_runtime.h>
#include <cuda_bf16.h>

// Problem constants (fixed by the reference)
#define NROWS 8192
#define NCOLS 8192
#define RB 32
#define CB 32
#define HID 100
#define DIO (RB*CB)
#define SPLITS 16                      // row-slots per (rb,cb) block
#define NITEMS (RB*CB*SPLITS)          // 16384 per-warp work items
#define CTAS_PER_SM 4
#define NB_CTAS (148*CTAS_PER_SM)      // 592, all co-resident (launch_bounds(256,4))

// Scratch (no cudaMalloc allowed)
__device__ float g_blk[RB*CB];
__device__ int   g_rowb[RB+1];
__device__ int   g_colb[CB+1];
__device__ int   g_work;
__device__ unsigned g_bar_arrive = 0;
__device__ volatile unsigned g_bar_gen = 0;

// Generation-based grid barrier: safe across graph replays (state self-resets),
// deadlock-free because all NB_CTAS are co-resident.
__device__ __forceinline__ void grid_barrier() {
    __syncthreads();
    if (threadIdx.x == 0) {
        __threadfence();
        unsigned gen = g_bar_gen;
        unsigned a = atomicAdd(&g_bar_arrive, 1u);
        if (a == NB_CTAS - 1u) {
            atomicExch(&g_bar_arrive, 0u);
            __threadfence();
            g_bar_gen = gen + 1u;
        } else {
            while (g_bar_gen == gen) { }
            __threadfence();
        }
    }
    __syncthreads();
}

__global__ __launch_bounds__(256, CTAS_PER_SM)
void k_fused(const float* __restrict__ X,
             const int* __restrict__ row_ids,
             const int* __restrict__ col_ids,
             const float* __restrict__ W1, const float* __restrict__ b1,
             const float* __restrict__ W2, const float* __restrict__ b2,
             const float* __restrict__ W3, const float* __restrict__ b3,
             float* __restrict__ out) {
    __shared__ int   srow[RB + 1];
    __shared__ int   scol[CB + 1];
    // MLP scratch (CTA 0 only, phase C)
    __shared__ float xs[DIO];
    __shared__ float h1p[800];
    __shared__ float h2p[1000];
    __shared__ float h1[HID];
    __shared__ float h2[HID];

    const int t = threadIdx.x;
    const int lane = t & 31;

    // ---------------- Phase A: setup (distributed) ----------------
    if (blockIdx.x < 32) {
        const bool rowpass = (blockIdx.x < 16);
        const int  slice   = rowpass ? blockIdx.x : (blockIdx.x - 16);
        const int  nb  = rowpass ? RB : CB;
        const int  n   = rowpass ? NROWS : NCOLS;
        const int* ids = rowpass ? row_ids : col_ids;
        int*   bnd = rowpass ? g_rowb : g_colb;
        float* o   = out + DIO + (rowpass ? 0 : (RB + 1));
        const int i = slice * 512 + t * 2;
        #pragma unroll
        for (int d = 0; d < 2; d++) {
            int g = i + d;
            if (g < n) {
                int cur  = ids[g];
                int prev = (g == 0) ? -1 : ids[g - 1];
                for (int k = prev + 1; k <= cur; k++) { bnd[k] = g; o[k] = (float)g; }
                if (g == n - 1)
                    for (int k = cur + 1; k <= nb; k++) { bnd[k] = n; o[k] = (float)n; }
            }
        }
    } else if (blockIdx.x == 32) {
        for (int j = t; j < DIO; j += 256) g_blk[j] = 0.0f;
    } else if (blockIdx.x == 33 && t == 0) {
        g_work = 0;
    }

    grid_barrier();

    // boundary arrays -> smem (L2-hot after barrier)
    if (t <= RB) srow[t] = g_rowb[t];
    else if (t >= 64 && t <= 64 + CB) scol[t - 64] = g_colb[t - 64];
    __syncthreads();

    // ---------------- Phase B: per-warp dynamic block-sum ----------------
    for (;;) {
        int item;
        if (lane == 0) item = atomicAdd(&g_work, 1);
        item = __shfl_sync(0xFFFFFFFFu, item, 0);
        if (item >= NITEMS) break;

        const int rb = item >> 9;
        const int cb = (item >> 4) & 31;
        const int ws = item & (SPLITS - 1);
        const int rlo = srow[rb], rhi = srow[rb + 1];
        const int clo = scol[cb], chi = scol[cb + 1];

        // 16B-aligned body [ca, ce), scalar head and tail
        int ca = (clo + 3) & ~3; if (ca > chi) ca = chi;
        int ce = chi & ~3;       if (ce < ca)  ce = ca;
        const int hN = ca - clo, tN = chi - ce;
        const int c4lo = ca >> 2, c4hi = ce >> 2;

        float a0 = 0.f, a1 = 0.f, a2 = 0.f, a3 = 0.f;
        int r = rlo + ws;

        // 4-row unrolled groups (rows strided by SPLITS, independent loads)
        for (; r + 3 * SPLITS < rhi; r += 4 * SPLITS) {
            const float* q0 = X + (size_t)r * NCOLS;
            const float* q1 = X + (size_t)(r +     SPLITS) * NCOLS;
            const float* q2 = X + (size_t)(r + 2 * SPLITS) * NCOLS;
            const float* q3 = X + (size_t)(r + 3 * SPLITS) * NCOLS;
            if (lane < hN) {
                a0 += q0[clo + lane]; a1 += q1[clo + lane];
                a2 += q2[clo + lane]; a3 += q3[clo + lane];
            }
            const float4* p0 = (const float4*)q0;
            const float4* p1 = (const float4*)q1;
            const float4* p2 = (const float4*)q2;
            const float4* p3 = (const float4*)q3;
            for (int c = c4lo + lane; c < c4hi; c += 32) {
                float4 v0 = p0[c];
                float4 v1 = p1[c];
                float4 v2 = p2[c];
                float4 v3 = p3[c];
                a0 += (v0.x + v0.y) + (v0.z + v0.w);
                a1 += (v1.x + v1.y) + (v1.z + v1.w);
                a2 += (v2.x + v2.y) + (v2.z + v2.w);
                a3 += (v3.x + v3.y) + (v3.z + v3.w);
            }
            if (lane < tN) {
                a0 += q0[ce + lane]; a1 += q1[ce + lane];
                a2 += q2[ce + lane]; a3 += q3[ce + lane];
            }
        }
        for (; r < rhi; r += SPLITS) {
            const float* q0 = X + (size_t)r * NCOLS;
            if (lane < hN) a0 += q0[clo + lane];
            const float4* p0 = (const float4*)q0;
            for (int c = c4lo + lane; c < c4hi; c += 32) {
                float4 v0 = p0[c];
                a0 += (v0.x + v0.y) + (v0.z + v0.w);
            }
            if (lane < tN) a0 += q0[ce + lane];
        }

        float acc = (a0 + a1) + (a2 + a3);
        #pragma unroll
        for (int o = 16; o; o >>= 1) acc += __shfl_xor_sync(0xFFFFFFFFu, acc, o);
        if (lane == 0) atomicAdd(&g_blk[rb * CB + cb], acc);   // REDG, no return dep
    }

    grid_barrier();

    // ---------------- Phase C: MLP (CTA 0 only) ----------------
    if (blockIdx.x != 0) return;

    // block mean (256 threads -> 4 bins each)
    #pragma unroll
    for (int d = 0; d < 4; d++) {
        int b = t + d * 256;
        int rb = b >> 5, cbi = b & 31;
        float rc = (float)(srow[rb + 1] - srow[rb]);
        float cc = (float)(scol[cbi + 1] - scol[cbi]);
        float cnt = fmaxf(rc * cc, 1.0f);
        xs[b] = g_blk[b] / cnt;
    }
    __syncthreads();

    // layer 1: h1 = relu(x @ W1 + b1), x[1024], W1[1024,100]; 8 K-slices x 100
    for (int u = t; u < 800; u += 256) {
        const int j  = u % HID;
        const int i0 = (u / HID) * 128;
        float acc = 0.f;
        #pragma unroll 16
        for (int i = 0; i < 128; i++)
            acc += xs[i0 + i] * W1[(size_t)(i0 + i) * HID + j];
        h1p[u] = acc;
    }
    __syncthreads();
    if (t < HID) {
        float a = b1[t];
        #pragma unroll
        for (int sl = 0; sl < 8; sl++) a += h1p[sl * HID + t];
        h1[t] = fmaxf(a, 0.f);
    }
    __syncthreads();

    // layer 2: h2 = relu(h1 @ W2 + b2), W2[100,100]; 10 K-slices x 100
    for (int u = t; u < 1000; u += 256) {
        const int j  = u % HID;
        const int i0 = (u / HID) * 10;
        float acc = 0.f;
        #pragma unroll
        for (int i = 0; i < 10; i++)
            acc += h1[i0 + i] * W2[(i0 + i) * HID + j];
        h2p[u] = acc;
    }
    __syncthreads();
    if (t < HID) {
        float a = b2[t];
        #pragma unroll
        for (int sl = 0; sl < 10; sl++) a += h2p[sl * HID + t];
        h2[t] = fmaxf(a, 0.f);
    }
    __syncthreads();

    // layer 3: out = sigmoid(h2 @ W3 + b3), W3[100,1024]
    #pragma unroll
    for (int d = 0; d < 4; d++) {
        int j = t + d * 256;
        float a = b3[j];
        #pragma unroll 20
        for (int i = 0; i < HID; i++) a += h2[i] * W3[(size_t)i * DIO + j];
        out[j] = 1.0f / (1.0f + __expf(-a));
    }
}

extern "C" void kernel_launch(void* const* d_in, const int* in_sizes, int n_in,
                              void* d_out, int out_size) {
    const float* X       = (const float*)d_in[0];
    const int*   row_ids = (const int*)  d_in[1];
    const int*   col_ids = (const int*)  d_in[2];
    const float* W1      = (const float*)d_in[3];
    const float* b1      = (const float*)d_in[4];
    const float* W2      = (const float*)d_in[5];
    const float* b2      = (const float*)d_in[6];
    const float* W3      = (const float*)d_in[7];
    const float* b3      = (const float*)d_in[8];
    float* out = (float*)d_out;

    k_fused<<<NB_CTAS, 256>>>(X, row_ids, col_ids, W1, b1, W2, b2, W3, b3, out);
}